// round 8
// baseline (speedup 1.0000x reference)
#include <cuda_runtime.h>
#include <cuda_bf16.h>
#include <mma.h>
#include <cstdint>
#include <math.h>

using namespace nvcuda;

#define EMB   1024
#define NH    16
#define DK    64
#define BB    2
#define SS    2048
#define NROW  (BB * SS)          // 4096

// ------------------------- scratch (device globals) ------------------------
__device__ float g_q[(size_t)NROW * EMB];
__device__ float g_k[(size_t)NROW * EMB];
__device__ float g_v[(size_t)NROW * EMB];
__device__ float g_o[(size_t)NROW * EMB];

// ---------------------- tf32 WMMA GEMM: Y = X @ W^T ------------------------
// X [M,K] row-major, W [N,K] row-major  ->  Y[m,n] = sum_k X[m,k] * W[n,k]
// Block tile 128x128, K-chunk 32. 256 threads = 8 warps, warp tile 32x64.
#define BM 128
#define BN 128
#define BK 32
#define LDS_K (BK + 4)           // 36 floats = 144B row stride (16B aligned)

__global__ __launch_bounds__(256)
void gemm_tf32(const float* __restrict__ X, const float* __restrict__ W,
               float* __restrict__ Y, int M, int N, int K)
{
    __shared__ float Xs[BM][LDS_K];
    __shared__ float Ws[BN][LDS_K];

    const int tid = threadIdx.x;
    const int wid = tid >> 5;
    const int wm  = wid & 3;          // 0..3  -> 32 rows of M
    const int wn  = wid >> 2;         // 0..1  -> 64 cols of N
    const int rowBase = blockIdx.y * BM;
    const int colBase = blockIdx.x * BN;

    wmma::fragment<wmma::accumulator, 16, 16, 8, float> acc[2][4];
    #pragma unroll
    for (int i = 0; i < 2; i++)
        #pragma unroll
        for (int j = 0; j < 4; j++)
            wmma::fill_fragment(acc[i][j], 0.0f);

    for (int k0 = 0; k0 < K; k0 += BK) {
        // stage 128x32 tiles of X and W (float4, fully coalesced)
        #pragma unroll
        for (int i = 0; i < 4; i++) {
            int v = tid + i * 256;            // 0..1023
            int r = v >> 3;                   // 0..127
            int c = (v & 7) * 4;              // 0,4,..,28
            *(float4*)&Xs[r][c] = *(const float4*)(X + (size_t)(rowBase + r) * K + k0 + c);
            *(float4*)&Ws[r][c] = *(const float4*)(W + (size_t)(colBase + r) * K + k0 + c);
        }
        __syncthreads();

        #pragma unroll
        for (int kk = 0; kk < BK; kk += 8) {
            wmma::fragment<wmma::matrix_a, 16, 16, 8, wmma::precision::tf32, wmma::row_major> a[2];
            wmma::fragment<wmma::matrix_b, 16, 16, 8, wmma::precision::tf32, wmma::col_major> b[4];
            #pragma unroll
            for (int i = 0; i < 2; i++) {
                wmma::load_matrix_sync(a[i], &Xs[wm * 32 + i * 16][kk], LDS_K);
                #pragma unroll
                for (int e = 0; e < a[i].num_elements; e++)
                    a[i].x[e] = wmma::__float_to_tf32(a[i].x[e]);
            }
            #pragma unroll
            for (int j = 0; j < 4; j++) {
                // col-major view: element (k, n) at ptr[n*LDS_K + k] = Ws[n0+n][kk+k] = W[n][k]
                wmma::load_matrix_sync(b[j], &Ws[wn * 64 + j * 16][kk], LDS_K);
                #pragma unroll
                for (int e = 0; e < b[j].num_elements; e++)
                    b[j].x[e] = wmma::__float_to_tf32(b[j].x[e]);
            }
            #pragma unroll
            for (int i = 0; i < 2; i++)
                #pragma unroll
                for (int j = 0; j < 4; j++)
                    wmma::mma_sync(acc[i][j], a[i], b[j], acc[i][j]);
        }
        __syncthreads();
    }

    #pragma unroll
    for (int i = 0; i < 2; i++)
        #pragma unroll
        for (int j = 0; j < 4; j++) {
            float* dst = Y + (size_t)(rowBase + wm * 32 + i * 16) * N + colBase + wn * 64 + j * 16;
            wmma::store_matrix_sync(dst, acc[i][j], N, wmma::mem_row_major);
        }
}

// ---------------------- flash attention (f32x2 SIMT) -----------------------
// packed f32x2 helpers (sm_100+ baseline)
#define FMA2(d, a, b, c) asm("fma.rn.f32x2 %0, %1, %2, %3;" : "=l"(d) : "l"(a), "l"(b), "l"(c))
#define MUL2(d, a, b)    asm("mul.rn.f32x2 %0, %1, %2;" : "=l"(d) : "l"(a), "l"(b))
#define ADD2(d, a, b)    asm("add.rn.f32x2 %0, %1, %2;" : "=l"(d) : "l"(a), "l"(b))
#define PACK2(d, u32)    asm("mov.b64 %0, {%1, %1};" : "=l"(d) : "r"(u32))
#define UNPK2(lo, hi, a) asm("mov.b64 {%0, %1}, %2;" : "=r"(lo), "=r"(hi) : "l"(a))

// grid (S/64, NH, BB), block 128: thread t -> query q=t>>1, half=t&1 (32 dims)
#define ATTN_SMEM_BYTES ((4096 + 4096 + 64 * 65) * 4 + 64 * 4)

__global__ __launch_bounds__(128)
void attn_kernel(const int* __restrict__ mask)
{
    extern __shared__ float smf[];
    float* Ks = smf;
    float* Vs = smf + 4096;
    float* Sc = smf + 8192;                 // stride 65
    int*   msk = (int*)(smf + 8192 + 64 * 65);

    const int qt = blockIdx.x, h = blockIdx.y, b = blockIdx.z;
    const int t = threadIdx.x;
    const int q = t >> 1;
    const int base = (t & 1) * 32;

    // stage Q tile into Ks, then grab this thread's 32-dim half as 16 packed pairs
    const float* qb = g_q + (size_t)(b * SS + qt * 64) * EMB + h * DK;
    #pragma unroll
    for (int i = 0; i < 8; i++) {
        int v = t + i * 128, r = v >> 4, dv = (v & 15) * 4;
        *(float4*)&Ks[r * 64 + dv] = *(const float4*)(qb + (size_t)r * EMB + dv);
    }
    __syncthreads();
    unsigned long long q2[16];
    {
        const ulonglong2* qp = (const ulonglong2*)&Ks[q * 64 + base];
        #pragma unroll
        for (int i = 0; i < 8; i++) { ulonglong2 w = qp[i]; q2[2 * i] = w.x; q2[2 * i + 1] = w.y; }
    }
    __syncthreads();

    unsigned long long acc2[16];
    #pragma unroll
    for (int i = 0; i < 16; i++) acc2[i] = 0ull;
    float m = -INFINITY, l = 0.f;

    for (int kt = 0; kt < SS / 64; kt++) {
        const float* kb = g_k + (size_t)(b * SS + kt * 64) * EMB + h * DK;
        const float* vb = g_v + (size_t)(b * SS + kt * 64) * EMB + h * DK;
        #pragma unroll
        for (int i = 0; i < 8; i++) {
            int v = t + i * 128, r = v >> 4, dv = (v & 15) * 4;
            *(float4*)&Ks[r * 64 + dv] = *(const float4*)(kb + (size_t)r * EMB + dv);
            *(float4*)&Vs[r * 64 + dv] = *(const float4*)(vb + (size_t)r * EMB + dv);
        }
        if (t < 64) msk[t] = mask[b * SS + kt * 64 + t];
        __syncthreads();

        // pass 1: scores (each thread does 32 of 64 dims, pair-reduce via shfl)
        float tmax = -INFINITY;
        #pragma unroll 2
        for (int j = 0; j < 64; j++) {
            const ulonglong2* kr = (const ulonglong2*)&Ks[j * 64 + base];
            unsigned long long sa = 0ull, sb = 0ull;
            #pragma unroll
            for (int i = 0; i < 8; i++) {
                ulonglong2 kv = kr[i];
                FMA2(sa, q2[2 * i], kv.x, sa);
                FMA2(sb, q2[2 * i + 1], kv.y, sb);
            }
            ADD2(sa, sa, sb);
            uint32_t slo, shi; UNPK2(slo, shi, sa);
            float s = __uint_as_float(slo) + __uint_as_float(shi);
            s += __shfl_xor_sync(0xffffffffu, s, 1);
            s *= 0.125f;
            if (msk[j] != 0) s = -1e9f;
            if ((t & 1) == 0) Sc[q * 65 + j] = s;
            tmax = fmaxf(tmax, s);
        }
        __syncwarp();

        float newm = fmaxf(m, tmax);
        float corr = __expf(m - newm);
        l *= corr;
        {
            unsigned long long c2; PACK2(c2, __float_as_uint(corr));
            #pragma unroll
            for (int i = 0; i < 16; i++) MUL2(acc2[i], acc2[i], c2);
        }

        // pass 2: p*V
        #pragma unroll 2
        for (int j = 0; j < 64; j++) {
            float p = __expf(Sc[q * 65 + j] - newm);
            l += p;
            unsigned long long p2; PACK2(p2, __float_as_uint(p));
            const ulonglong2* vr = (const ulonglong2*)&Vs[j * 64 + base];
            #pragma unroll
            for (int i = 0; i < 8; i++) {
                ulonglong2 vv = vr[i];
                FMA2(acc2[2 * i],     p2, vv.x, acc2[2 * i]);
                FMA2(acc2[2 * i + 1], p2, vv.y, acc2[2 * i + 1]);
            }
        }
        m = newm;
        __syncthreads();
    }

    // normalize + stage + coalesced store
    float inv_l = 1.0f / l;
    #pragma unroll
    for (int i = 0; i < 16; i++) {
        uint32_t alo, ahi; UNPK2(alo, ahi, acc2[i]);
        Sc[q * 65 + base + 2 * i]     = __uint_as_float(alo) * inv_l;
        Sc[q * 65 + base + 2 * i + 1] = __uint_as_float(ahi) * inv_l;
    }
    __syncthreads();

    float* ob = g_o + (size_t)(b * SS + qt * 64) * EMB + h * DK;
    #pragma unroll
    for (int i = 0; i < 8; i++) {
        int v = t + i * 128, r = v >> 4, dv = (v & 15) * 4;
        float4 val = make_float4(Sc[r * 65 + dv + 0], Sc[r * 65 + dv + 1],
                                 Sc[r * 65 + dv + 2], Sc[r * 65 + dv + 3]);
        *(float4*)(ob + (size_t)r * EMB + dv) = val;
    }
}

// ------------------------------- launch ------------------------------------
extern "C" void kernel_launch(void* const* d_in, const int* in_sizes, int n_in,
                              void* d_out, int out_size)
{
    const float* x    = (const float*)d_in[0];
    const int*   mask = (const int*)d_in[1];
    const float* wq   = (const float*)d_in[2];
    const float* wk   = (const float*)d_in[3];
    const float* wv   = (const float*)d_in[4];
    const float* wo   = (const float*)d_in[5];
    float* out = (float*)d_out;

    float *q, *k, *v, *o;
    cudaGetSymbolAddress((void**)&q, g_q);
    cudaGetSymbolAddress((void**)&k, g_k);
    cudaGetSymbolAddress((void**)&v, g_v);
    cudaGetSymbolAddress((void**)&o, g_o);

    cudaFuncSetAttribute(attn_kernel, cudaFuncAttributeMaxDynamicSharedMemorySize,
                         ATTN_SMEM_BYTES);

    dim3 gg(EMB / BN, NROW / BM);     // (8, 32)
    gemm_tf32<<<gg, 256>>>(x, wq, q, NROW, EMB, EMB);
    gemm_tf32<<<gg, 256>>>(x, wk, k, NROW, EMB, EMB);
    gemm_tf32<<<gg, 256>>>(x, wv, v, NROW, EMB, EMB);

    attn_kernel<<<dim3(SS / 64, NH, BB), 128, ATTN_SMEM_BYTES>>>(mask);

    gemm_tf32<<<gg, 256>>>(o, wo, out, NROW, EMB, EMB);
}

// round 9
// speedup vs baseline: 1.7815x; 1.7815x over previous
#include <cuda_runtime.h>
#include <cuda_bf16.h>
#include <mma.h>
#include <cstdint>
#include <math.h>

using namespace nvcuda;

#define EMB   1024
#define NH    16
#define DK    64
#define BB    2
#define SS    2048
#define NROW  (BB * SS)          // 4096

// ------------------------- scratch (device globals) ------------------------
__device__ float g_q[(size_t)NROW * EMB];
__device__ float g_k[(size_t)NROW * EMB];
__device__ float g_v[(size_t)NROW * EMB];
__device__ float g_o[(size_t)NROW * EMB];

__device__ __nv_bfloat16 g_xhi[(size_t)NROW * EMB];
__device__ __nv_bfloat16 g_xlo[(size_t)NROW * EMB];
__device__ __nv_bfloat16 g_ohi[(size_t)NROW * EMB];
__device__ __nv_bfloat16 g_olo[(size_t)NROW * EMB];
__device__ __nv_bfloat16 g_wqhi[(size_t)EMB * EMB];
__device__ __nv_bfloat16 g_wqlo[(size_t)EMB * EMB];
__device__ __nv_bfloat16 g_wkhi[(size_t)EMB * EMB];
__device__ __nv_bfloat16 g_wklo[(size_t)EMB * EMB];
__device__ __nv_bfloat16 g_wvhi[(size_t)EMB * EMB];
__device__ __nv_bfloat16 g_wvlo[(size_t)EMB * EMB];
__device__ __nv_bfloat16 g_wohi[(size_t)EMB * EMB];
__device__ __nv_bfloat16 g_wolo[(size_t)EMB * EMB];

// ---------------------- fp32 -> bf16 hi/lo split ---------------------------
__global__ __launch_bounds__(256)
void split_bf16(const float* __restrict__ in, __nv_bfloat16* __restrict__ hi,
                __nv_bfloat16* __restrict__ lo, int n4)
{
    int i = blockIdx.x * blockDim.x + threadIdx.x;
    if (i >= n4) return;
    float4 v = ((const float4*)in)[i];
    __nv_bfloat16 h0 = __float2bfloat16(v.x);
    __nv_bfloat16 h1 = __float2bfloat16(v.y);
    __nv_bfloat16 h2 = __float2bfloat16(v.z);
    __nv_bfloat16 h3 = __float2bfloat16(v.w);
    __nv_bfloat16 l0 = __float2bfloat16(v.x - __bfloat162float(h0));
    __nv_bfloat16 l1 = __float2bfloat16(v.y - __bfloat162float(h1));
    __nv_bfloat16 l2 = __float2bfloat16(v.z - __bfloat162float(h2));
    __nv_bfloat16 l3 = __float2bfloat16(v.w - __bfloat162float(h3));
    ((ushort4*)hi)[i] = make_ushort4(__bfloat16_as_ushort(h0), __bfloat16_as_ushort(h1),
                                     __bfloat16_as_ushort(h2), __bfloat16_as_ushort(h3));
    ((ushort4*)lo)[i] = make_ushort4(__bfloat16_as_ushort(l0), __bfloat16_as_ushort(l1),
                                     __bfloat16_as_ushort(l2), __bfloat16_as_ushort(l3));
}

// ------------- bf16 hi/lo 3-pass WMMA GEMM: Y = X @ W^T --------------------
// Y[m,n] = sum_k X[m,k]*W[n,k].  D = Xhi*Whi + Xhi*Wlo + Xlo*Whi (fp32 accum)
// Block tile 128x128, K-chunk 32. 4 warps, each 64x64 warp tile.
#define LDB 40                   // bf16 elems per smem row (80B, conflict-free)

__global__ __launch_bounds__(128)
void gemm_bf16hl(const __nv_bfloat16* __restrict__ Ahi, const __nv_bfloat16* __restrict__ Alo,
                 const __nv_bfloat16* __restrict__ Bhi, const __nv_bfloat16* __restrict__ Blo,
                 float* __restrict__ Y, int M, int N, int K)
{
    __shared__ __nv_bfloat16 sAh[128 * LDB];
    __shared__ __nv_bfloat16 sAl[128 * LDB];
    __shared__ __nv_bfloat16 sBh[128 * LDB];
    __shared__ __nv_bfloat16 sBl[128 * LDB];

    const int tid = threadIdx.x;
    const int wid = tid >> 5;
    const int wm  = wid & 1;          // 0..1 -> 64 rows of M
    const int wn  = wid >> 1;         // 0..1 -> 64 cols of N
    const int rowBase = blockIdx.y * 128;
    const int colBase = blockIdx.x * 128;

    wmma::fragment<wmma::accumulator, 16, 16, 16, float> acc[4][4];
    #pragma unroll
    for (int i = 0; i < 4; i++)
        #pragma unroll
        for (int j = 0; j < 4; j++)
            wmma::fill_fragment(acc[i][j], 0.0f);

    for (int k0 = 0; k0 < K; k0 += 32) {
        // stage 128x32 bf16 tiles (hi+lo for A and B), float4 = 8 bf16
        #pragma unroll
        for (int i = 0; i < 4; i++) {
            int idx = tid + i * 128;          // 0..511
            int r   = idx >> 2;               // 0..127
            int c8  = (idx & 3) * 8;          // 0,8,16,24
            size_t goA = (size_t)(rowBase + r) * K + k0 + c8;
            size_t goB = (size_t)(colBase + r) * K + k0 + c8;
            *(float4*)&sAh[r * LDB + c8] = *(const float4*)(Ahi + goA);
            *(float4*)&sAl[r * LDB + c8] = *(const float4*)(Alo + goA);
            *(float4*)&sBh[r * LDB + c8] = *(const float4*)(Bhi + goB);
            *(float4*)&sBl[r * LDB + c8] = *(const float4*)(Blo + goB);
        }
        __syncthreads();

        #pragma unroll
        for (int pass = 0; pass < 3; pass++) {
            const __nv_bfloat16* pa = (pass == 2) ? sAl : sAh;
            const __nv_bfloat16* pb = (pass == 1) ? sBl : sBh;
            #pragma unroll
            for (int ks = 0; ks < 2; ks++) {
                wmma::fragment<wmma::matrix_a, 16, 16, 16, __nv_bfloat16, wmma::row_major> a[4];
                wmma::fragment<wmma::matrix_b, 16, 16, 16, __nv_bfloat16, wmma::col_major> b[4];
                #pragma unroll
                for (int i = 0; i < 4; i++)
                    wmma::load_matrix_sync(a[i], pa + (wm * 64 + i * 16) * LDB + ks * 16, LDB);
                #pragma unroll
                for (int j = 0; j < 4; j++)
                    wmma::load_matrix_sync(b[j], pb + (wn * 64 + j * 16) * LDB + ks * 16, LDB);
                #pragma unroll
                for (int i = 0; i < 4; i++)
                    #pragma unroll
                    for (int j = 0; j < 4; j++)
                        wmma::mma_sync(acc[i][j], a[i], b[j], acc[i][j]);
            }
        }
        __syncthreads();
    }

    #pragma unroll
    for (int i = 0; i < 4; i++)
        #pragma unroll
        for (int j = 0; j < 4; j++) {
            float* dst = Y + (size_t)(rowBase + wm * 64 + i * 16) * N + colBase + wn * 64 + j * 16;
            wmma::store_matrix_sync(dst, acc[i][j], N, wmma::mem_row_major);
        }
}

// ---------------------- flash attention (f32x2 SIMT) -----------------------
#define FMA2(d, a, b, c) asm("fma.rn.f32x2 %0, %1, %2, %3;" : "=l"(d) : "l"(a), "l"(b), "l"(c))
#define MUL2(d, a, b)    asm("mul.rn.f32x2 %0, %1, %2;" : "=l"(d) : "l"(a), "l"(b))
#define ADD2(d, a, b)    asm("add.rn.f32x2 %0, %1, %2;" : "=l"(d) : "l"(a), "l"(b))
#define PACK2(d, u32)    asm("mov.b64 %0, {%1, %1};" : "=l"(d) : "r"(u32))
#define UNPK2(lo, hi, a) asm("mov.b64 {%0, %1}, %2;" : "=r"(lo), "=r"(hi) : "l"(a))

// grid (S/64, NH, BB), block 128: thread t -> query q=t>>1, par=t&1.
// Thread covers float4 chunks (2i+par), i<8 -> partner lanes read ADJACENT
// 16B (conflict-free broadcast), not 128B-apart (same-bank conflict).
#define SC_LD 68                    // score/stage row stride (floats, 16B mult)
#define ATTN_SMEM_BYTES ((4096 + 4096 + 64 * SC_LD) * 4 + 64 * 4)

__global__ __launch_bounds__(128)
void attn_kernel(const int* __restrict__ mask)
{
    extern __shared__ float smf[];
    float* Ks = smf;
    float* Vs = smf + 4096;
    float* Sc = smf + 8192;                 // stride SC_LD
    int*   msk = (int*)(smf + 8192 + 64 * SC_LD);

    const int qt = blockIdx.x, h = blockIdx.y, b = blockIdx.z;
    const int t = threadIdx.x;
    const int q = t >> 1;
    const int par = t & 1;

    // stage Q tile into Ks, grab this thread's 8 interleaved float4 chunks
    const float* qb = g_q + (size_t)(b * SS + qt * 64) * EMB + h * DK;
    #pragma unroll
    for (int i = 0; i < 8; i++) {
        int v = t + i * 128, r = v >> 4, dv = (v & 15) * 4;
        *(float4*)&Ks[r * 64 + dv] = *(const float4*)(qb + (size_t)r * EMB + dv);
    }
    __syncthreads();
    unsigned long long q2[16];
    #pragma unroll
    for (int i = 0; i < 8; i++) {
        ulonglong2 w = *(const ulonglong2*)&Ks[q * 64 + (2 * i + par) * 4];
        q2[2 * i] = w.x; q2[2 * i + 1] = w.y;
    }
    __syncthreads();

    unsigned long long acc2[16];
    #pragma unroll
    for (int i = 0; i < 16; i++) acc2[i] = 0ull;
    float m = -INFINITY, l = 0.f;

    for (int kt = 0; kt < SS / 64; kt++) {
        const float* kb = g_k + (size_t)(b * SS + kt * 64) * EMB + h * DK;
        const float* vb = g_v + (size_t)(b * SS + kt * 64) * EMB + h * DK;
        #pragma unroll
        for (int i = 0; i < 8; i++) {
            int v = t + i * 128, r = v >> 4, dv = (v & 15) * 4;
            *(float4*)&Ks[r * 64 + dv] = *(const float4*)(kb + (size_t)r * EMB + dv);
            *(float4*)&Vs[r * 64 + dv] = *(const float4*)(vb + (size_t)r * EMB + dv);
        }
        if (t < 64) msk[t] = mask[b * SS + kt * 64 + t];
        __syncthreads();

        // pass 1: scores (32 of 64 dims per thread, pair-reduce via shfl)
        float tmax = -INFINITY;
        #pragma unroll 2
        for (int j = 0; j < 64; j++) {
            const float* kr = &Ks[j * 64];
            unsigned long long sa = 0ull, sb = 0ull;
            #pragma unroll
            for (int i = 0; i < 8; i++) {
                ulonglong2 kv = *(const ulonglong2*)&kr[(2 * i + par) * 4];
                FMA2(sa, q2[2 * i], kv.x, sa);
                FMA2(sb, q2[2 * i + 1], kv.y, sb);
            }
            ADD2(sa, sa, sb);
            uint32_t slo, shi; UNPK2(slo, shi, sa);
            float s = __uint_as_float(slo) + __uint_as_float(shi);
            s += __shfl_xor_sync(0xffffffffu, s, 1);
            s *= 0.125f;
            if (msk[j] != 0) s = -1e9f;
            if (par == 0) Sc[q * SC_LD + j] = s;
            tmax = fmaxf(tmax, s);
        }
        __syncwarp();

        float newm = fmaxf(m, tmax);
        float corr = __expf(m - newm);
        l *= corr;
        {
            unsigned long long c2; PACK2(c2, __float_as_uint(corr));
            #pragma unroll
            for (int i = 0; i < 16; i++) MUL2(acc2[i], acc2[i], c2);
        }

        // pass 2: p*V
        #pragma unroll 2
        for (int j = 0; j < 64; j++) {
            float p = __expf(Sc[q * SC_LD + j] - newm);
            l += p;
            unsigned long long p2; PACK2(p2, __float_as_uint(p));
            const float* vr = &Vs[j * 64];
            #pragma unroll
            for (int i = 0; i < 8; i++) {
                ulonglong2 vv = *(const ulonglong2*)&vr[(2 * i + par) * 4];
                FMA2(acc2[2 * i],     p2, vv.x, acc2[2 * i]);
                FMA2(acc2[2 * i + 1], p2, vv.y, acc2[2 * i + 1]);
            }
        }
        m = newm;
        __syncthreads();
    }

    // normalize + stage (float4, 16B-aligned rows) + coalesced store
    float inv_l = 1.0f / l;
    #pragma unroll
    for (int i = 0; i < 8; i++) {
        uint32_t alo0, ahi0, alo1, ahi1;
        UNPK2(alo0, ahi0, acc2[2 * i]);
        UNPK2(alo1, ahi1, acc2[2 * i + 1]);
        float4 val = make_float4(__uint_as_float(alo0) * inv_l, __uint_as_float(ahi0) * inv_l,
                                 __uint_as_float(alo1) * inv_l, __uint_as_float(ahi1) * inv_l);
        *(float4*)&Sc[q * SC_LD + (2 * i + par) * 4] = val;
    }
    __syncthreads();

    float* ob = g_o + (size_t)(b * SS + qt * 64) * EMB + h * DK;
    #pragma unroll
    for (int i = 0; i < 8; i++) {
        int v = t + i * 128, r = v >> 4, dv = (v & 15) * 4;
        *(float4*)(ob + (size_t)r * EMB + dv) = *(float4*)&Sc[r * SC_LD + dv];
    }
}

// ------------------------------- launch ------------------------------------
extern "C" void kernel_launch(void* const* d_in, const int* in_sizes, int n_in,
                              void* d_out, int out_size)
{
    const float* x    = (const float*)d_in[0];
    const int*   mask = (const int*)d_in[1];
    const float* wq   = (const float*)d_in[2];
    const float* wk   = (const float*)d_in[3];
    const float* wv   = (const float*)d_in[4];
    const float* wo   = (const float*)d_in[5];
    float* out = (float*)d_out;

    float *q, *k, *v, *o;
    cudaGetSymbolAddress((void**)&q, g_q);
    cudaGetSymbolAddress((void**)&k, g_k);
    cudaGetSymbolAddress((void**)&v, g_v);
    cudaGetSymbolAddress((void**)&o, g_o);
    __nv_bfloat16 *xhi, *xlo, *ohi, *olo;
    __nv_bfloat16 *wqh, *wql, *wkh, *wkl, *wvh, *wvl, *woh, *wol;
    cudaGetSymbolAddress((void**)&xhi, g_xhi);  cudaGetSymbolAddress((void**)&xlo, g_xlo);
    cudaGetSymbolAddress((void**)&ohi, g_ohi);  cudaGetSymbolAddress((void**)&olo, g_olo);
    cudaGetSymbolAddress((void**)&wqh, g_wqhi); cudaGetSymbolAddress((void**)&wql, g_wqlo);
    cudaGetSymbolAddress((void**)&wkh, g_wkhi); cudaGetSymbolAddress((void**)&wkl, g_wklo);
    cudaGetSymbolAddress((void**)&wvh, g_wvhi); cudaGetSymbolAddress((void**)&wvl, g_wvlo);
    cudaGetSymbolAddress((void**)&woh, g_wohi); cudaGetSymbolAddress((void**)&wol, g_wolo);

    cudaFuncSetAttribute(attn_kernel, cudaFuncAttributeMaxDynamicSharedMemorySize,
                         ATTN_SMEM_BYTES);

    const int nx4 = NROW * EMB / 4;     // 1048576
    const int nw4 = EMB * EMB / 4;      // 262144
    split_bf16<<<nx4 / 256, 256>>>(x,  xhi, xlo, nx4);
    split_bf16<<<nw4 / 256, 256>>>(wq, wqh, wql, nw4);
    split_bf16<<<nw4 / 256, 256>>>(wk, wkh, wkl, nw4);
    split_bf16<<<nw4 / 256, 256>>>(wv, wvh, wvl, nw4);
    split_bf16<<<nw4 / 256, 256>>>(wo, woh, wol, nw4);

    dim3 gg(EMB / 128, NROW / 128);     // (8, 32)
    gemm_bf16hl<<<gg, 128>>>(xhi, xlo, wqh, wql, q, NROW, EMB, EMB);
    gemm_bf16hl<<<gg, 128>>>(xhi, xlo, wkh, wkl, k, NROW, EMB, EMB);
    gemm_bf16hl<<<gg, 128>>>(xhi, xlo, wvh, wvl, v, NROW, EMB, EMB);

    attn_kernel<<<dim3(SS / 64, NH, BB), 128, ATTN_SMEM_BYTES>>>(mask);

    split_bf16<<<nx4 / 256, 256>>>(o, ohi, olo, nx4);
    gemm_bf16hl<<<gg, 128>>>(ohi, olo, woh, wol, out, NROW, EMB, EMB);
}

// round 13
// speedup vs baseline: 2.5957x; 1.4570x over previous
#include <cuda_runtime.h>
#include <cuda_bf16.h>
#include <mma.h>
#include <cstdint>
#include <math.h>

using namespace nvcuda;

#define EMB   1024
#define NH    16
#define DK    64
#define BB    2
#define SS    2048
#define NROW  (BB * SS)          // 4096

// ------------------------- scratch (device globals) ------------------------
__device__ __nv_bfloat16 g_xhi[(size_t)NROW * EMB];
__device__ __nv_bfloat16 g_xlo[(size_t)NROW * EMB];
__device__ __nv_bfloat16 g_qhi[(size_t)NROW * EMB];
__device__ __nv_bfloat16 g_qlo[(size_t)NROW * EMB];
__device__ __nv_bfloat16 g_khi[(size_t)NROW * EMB];
__device__ __nv_bfloat16 g_klo[(size_t)NROW * EMB];
__device__ __nv_bfloat16 g_vhi[(size_t)NROW * EMB];
__device__ __nv_bfloat16 g_vlo[(size_t)NROW * EMB];
__device__ __nv_bfloat16 g_ohi[(size_t)NROW * EMB];
__device__ __nv_bfloat16 g_olo[(size_t)NROW * EMB];
__device__ __nv_bfloat16 g_wqhi[(size_t)EMB * EMB];
__device__ __nv_bfloat16 g_wqlo[(size_t)EMB * EMB];
__device__ __nv_bfloat16 g_wkhi[(size_t)EMB * EMB];
__device__ __nv_bfloat16 g_wklo[(size_t)EMB * EMB];
__device__ __nv_bfloat16 g_wvhi[(size_t)EMB * EMB];
__device__ __nv_bfloat16 g_wvlo[(size_t)EMB * EMB];
__device__ __nv_bfloat16 g_wohi[(size_t)EMB * EMB];
__device__ __nv_bfloat16 g_wolo[(size_t)EMB * EMB];

__device__ __forceinline__ void split1(float f, ushort& h, ushort& l) {
    __nv_bfloat16 hh = __float2bfloat16(f);
    h = __bfloat16_as_ushort(hh);
    l = __bfloat16_as_ushort(__float2bfloat16(f - __bfloat162float(hh)));
}

// ---------------------- fp32 -> bf16 hi/lo split ---------------------------
__global__ __launch_bounds__(256)
void split_bf16(const float* __restrict__ in, __nv_bfloat16* __restrict__ hi,
                __nv_bfloat16* __restrict__ lo, int n4)
{
    int i = blockIdx.x * blockDim.x + threadIdx.x;
    if (i >= n4) return;
    float4 v = ((const float4*)in)[i];
    ushort4 uh, ul;
    split1(v.x, uh.x, ul.x);
    split1(v.y, uh.y, ul.y);
    split1(v.z, uh.z, ul.z);
    split1(v.w, uh.w, ul.w);
    ((ushort4*)hi)[i] = uh;
    ((ushort4*)lo)[i] = ul;
}

// ------------- bf16 hi/lo 3-pass WMMA GEMM: Y = X @ W^T --------------------
#define LDB 40                   // bf16 elems per smem row (80B, conflict-free)

template<bool SPLIT_OUT>
__global__ __launch_bounds__(128)
void gemm_bf16hl(const __nv_bfloat16* __restrict__ Ahi, const __nv_bfloat16* __restrict__ Alo,
                 const __nv_bfloat16* __restrict__ Bhi, const __nv_bfloat16* __restrict__ Blo,
                 float* __restrict__ Y,
                 __nv_bfloat16* __restrict__ Yhi, __nv_bfloat16* __restrict__ Ylo,
                 int M, int N, int K)
{
    __shared__ __nv_bfloat16 sAh[128 * LDB];
    __shared__ __nv_bfloat16 sAl[128 * LDB];
    __shared__ __nv_bfloat16 sBh[128 * LDB];
    __shared__ __nv_bfloat16 sBl[128 * LDB];
    __shared__ float sEpi[4 * 256];

    const int tid = threadIdx.x;
    const int wid = tid >> 5;
    const int lane = tid & 31;
    const int wm  = wid & 1;
    const int wn  = wid >> 1;
    const int rowBase = blockIdx.y * 128;
    const int colBase = blockIdx.x * 128;

    wmma::fragment<wmma::accumulator, 16, 16, 16, float> acc[4][4];
    #pragma unroll
    for (int i = 0; i < 4; i++)
        #pragma unroll
        for (int j = 0; j < 4; j++)
            wmma::fill_fragment(acc[i][j], 0.0f);

    for (int k0 = 0; k0 < K; k0 += 32) {
        #pragma unroll
        for (int i = 0; i < 4; i++) {
            int idx = tid + i * 128;
            int r   = idx >> 2;
            int c8  = (idx & 3) * 8;
            size_t goA = (size_t)(rowBase + r) * K + k0 + c8;
            size_t goB = (size_t)(colBase + r) * K + k0 + c8;
            *(float4*)&sAh[r * LDB + c8] = *(const float4*)(Ahi + goA);
            *(float4*)&sAl[r * LDB + c8] = *(const float4*)(Alo + goA);
            *(float4*)&sBh[r * LDB + c8] = *(const float4*)(Bhi + goB);
            *(float4*)&sBl[r * LDB + c8] = *(const float4*)(Blo + goB);
        }
        __syncthreads();

        #pragma unroll
        for (int pass = 0; pass < 3; pass++) {
            const __nv_bfloat16* pa = (pass == 2) ? sAl : sAh;
            const __nv_bfloat16* pb = (pass == 1) ? sBl : sBh;
            #pragma unroll
            for (int ks = 0; ks < 2; ks++) {
                wmma::fragment<wmma::matrix_a, 16, 16, 16, __nv_bfloat16, wmma::row_major> a[4];
                wmma::fragment<wmma::matrix_b, 16, 16, 16, __nv_bfloat16, wmma::col_major> b[4];
                #pragma unroll
                for (int i = 0; i < 4; i++)
                    wmma::load_matrix_sync(a[i], pa + (wm * 64 + i * 16) * LDB + ks * 16, LDB);
                #pragma unroll
                for (int j = 0; j < 4; j++)
                    wmma::load_matrix_sync(b[j], pb + (wn * 64 + j * 16) * LDB + ks * 16, LDB);
                #pragma unroll
                for (int i = 0; i < 4; i++)
                    #pragma unroll
                    for (int j = 0; j < 4; j++)
                        wmma::mma_sync(acc[i][j], a[i], b[j], acc[i][j]);
            }
        }
        __syncthreads();
    }

    if constexpr (!SPLIT_OUT) {
        #pragma unroll
        for (int i = 0; i < 4; i++)
            #pragma unroll
            for (int j = 0; j < 4; j++) {
                float* dst = Y + (size_t)(rowBase + wm * 64 + i * 16) * N + colBase + wn * 64 + j * 16;
                wmma::store_matrix_sync(dst, acc[i][j], N, wmma::mem_row_major);
            }
    } else {
        float* sc = sEpi + wid * 256;
        #pragma unroll
        for (int i = 0; i < 4; i++)
            #pragma unroll
            for (int j = 0; j < 4; j++) {
                wmma::store_matrix_sync(sc, acc[i][j], 16, wmma::mem_row_major);
                __syncwarp();
                int row = lane >> 1;
                int c0  = (lane & 1) * 8;
                const float* sp = sc + row * 16 + c0;
                ushort4 uh, ul, uh2, ul2;
                split1(sp[0], uh.x, ul.x); split1(sp[1], uh.y, ul.y);
                split1(sp[2], uh.z, ul.z); split1(sp[3], uh.w, ul.w);
                split1(sp[4], uh2.x, ul2.x); split1(sp[5], uh2.y, ul2.y);
                split1(sp[6], uh2.z, ul2.z); split1(sp[7], uh2.w, ul2.w);
                size_t go = (size_t)(rowBase + wm * 64 + i * 16 + row) * N + colBase + wn * 64 + j * 16 + c0;
                *(ushort4*)(Yhi + go) = uh;
                *(ushort4*)(Ylo + go) = ul;
                *(ushort4*)(Yhi + go + 4) = uh2;
                *(ushort4*)(Ylo + go + 4) = ul2;
                __syncwarp();
            }
    }
}

// ---------------------- WMMA flash attention --------------------------------
// 64 queries per block, 128 threads / 4 warps. Warp w owns query rows 16w..16w+15.
#define QROWS 64
#define KTILE 64
#define LQ 72
#define LS 68

#define OFF_QHI 0
#define OFF_QLO (OFF_QHI + QROWS * LQ * 2)
#define OFF_KHI (OFF_QLO + QROWS * LQ * 2)
#define OFF_KLO (OFF_KHI + KTILE * LQ * 2)
#define OFF_VHI (OFF_KLO + KTILE * LQ * 2)
#define OFF_VLO (OFF_VHI + KTILE * LQ * 2)
#define OFF_S   (OFF_VLO + KTILE * LQ * 2)
#define OFF_PHI (OFF_S   + QROWS * LS * 4)
#define OFF_PLO (OFF_PHI + QROWS * LQ * 2)
#define OFF_O   (OFF_PLO + QROWS * LQ * 2)
#define OFF_MSK (OFF_O   + QROWS * LS * 4)
#define ATTN_SMEM (OFF_MSK + KTILE * 4)    // 108,800 B -> 2 CTAs/SM

__global__ __launch_bounds__(128)
void attn_wmma(const int* __restrict__ mask)
{
    extern __shared__ char smc[];
    __nv_bfloat16* Qhi = (__nv_bfloat16*)(smc + OFF_QHI);
    __nv_bfloat16* Qlo = (__nv_bfloat16*)(smc + OFF_QLO);
    __nv_bfloat16* Khi = (__nv_bfloat16*)(smc + OFF_KHI);
    __nv_bfloat16* Klo = (__nv_bfloat16*)(smc + OFF_KLO);
    __nv_bfloat16* Vhi = (__nv_bfloat16*)(smc + OFF_VHI);
    __nv_bfloat16* Vlo = (__nv_bfloat16*)(smc + OFF_VLO);
    float*         S   = (float*)(smc + OFF_S);
    __nv_bfloat16* Phi = (__nv_bfloat16*)(smc + OFF_PHI);
    __nv_bfloat16* Plo = (__nv_bfloat16*)(smc + OFF_PLO);
    float*         O   = (float*)(smc + OFF_O);
    int*           msk = (int*)(smc + OFF_MSK);

    const int qt = blockIdx.x, h = blockIdx.y, b = blockIdx.z;
    const int t = threadIdx.x;          // 0..127
    const int wid = t >> 5;             // 0..3
    const int row_t = t >> 1;           // 0..63 (warp-local: rows 16w..16w+15)
    const int par = t & 1;

    for (int i = t; i < QROWS * LS; i += 128) O[i] = 0.0f;

    // stage Q hi/lo (64 rows x 64 bf16)
    #pragma unroll
    for (int i = 0; i < 4; i++) {
        int idx = t + i * 128;          // 0..511
        int r = idx >> 3, c = idx & 7;
        size_t go = (size_t)(b * SS + qt * QROWS + r) * EMB + h * DK + c * 8;
        *(float4*)&Qhi[r * LQ + c * 8] = *(const float4*)(g_qhi + go);
        *(float4*)&Qlo[r * LQ + c * 8] = *(const float4*)(g_qlo + go);
    }
    __syncthreads();

    float m = -INFINITY, l = 0.0f;

    for (int kt = 0; kt < SS / KTILE; kt++) {
        // stage K/V hi/lo (64 rows x 64 bf16 each) + mask
        #pragma unroll
        for (int i = 0; i < 4; i++) {
            int idx = t + i * 128;      // 0..511
            int r = idx >> 3, c = idx & 7;
            size_t go = (size_t)(b * SS + kt * KTILE + r) * EMB + h * DK + c * 8;
            *(float4*)&Khi[r * LQ + c * 8] = *(const float4*)(g_khi + go);
            *(float4*)&Klo[r * LQ + c * 8] = *(const float4*)(g_klo + go);
            *(float4*)&Vhi[r * LQ + c * 8] = *(const float4*)(g_vhi + go);
            *(float4*)&Vlo[r * LQ + c * 8] = *(const float4*)(g_vlo + go);
        }
        if (t < KTILE) msk[t] = mask[b * SS + kt * KTILE + t];
        __syncthreads();

        // S = Q K^T (warp strip 16 x 64)
        {
            wmma::fragment<wmma::accumulator, 16, 16, 16, float> sacc[4];
            #pragma unroll
            for (int j = 0; j < 4; j++) wmma::fill_fragment(sacc[j], 0.0f);
            #pragma unroll
            for (int pass = 0; pass < 3; pass++) {
                const __nv_bfloat16* qa = (pass == 2) ? Qlo : Qhi;
                const __nv_bfloat16* kb = (pass == 1) ? Klo : Khi;
                #pragma unroll
                for (int ks = 0; ks < 4; ks++) {
                    wmma::fragment<wmma::matrix_a, 16, 16, 16, __nv_bfloat16, wmma::row_major> a;
                    wmma::load_matrix_sync(a, qa + (wid * 16) * LQ + ks * 16, LQ);
                    #pragma unroll
                    for (int j = 0; j < 4; j++) {
                        wmma::fragment<wmma::matrix_b, 16, 16, 16, __nv_bfloat16, wmma::col_major> bf;
                        wmma::load_matrix_sync(bf, kb + (j * 16) * LQ + ks * 16, LQ);
                        wmma::mma_sync(sacc[j], a, bf, sacc[j]);
                    }
                }
            }
            #pragma unroll
            for (int j = 0; j < 4; j++)
                wmma::store_matrix_sync(S + (wid * 16) * LS + j * 16, sacc[j], LS, wmma::mem_row_major);
        }
        __syncwarp();

        // softmax (rows warp-local)
        float sv[32];
        float tmax = -INFINITY;
        #pragma unroll
        for (int c = 0; c < 32; c++) {
            float s = S[row_t * LS + par * 32 + c] * 0.125f;
            if (msk[par * 32 + c] != 0) s = -1e9f;
            sv[c] = s;
            tmax = fmaxf(tmax, s);
        }
        tmax = fmaxf(tmax, __shfl_xor_sync(0xffffffffu, tmax, 1));
        float newm = fmaxf(m, tmax);
        float corr = __expf(m - newm);
        float psum = 0.0f;
        #pragma unroll
        for (int c = 0; c < 32; c++) {
            float p = __expf(sv[c] - newm);
            psum += p;
            __nv_bfloat16 ph = __float2bfloat16(p);
            Phi[row_t * LQ + par * 32 + c] = ph;
            Plo[row_t * LQ + par * 32 + c] = __float2bfloat16(p - __bfloat162float(ph));
        }
        psum += __shfl_xor_sync(0xffffffffu, psum, 1);
        l = l * corr + psum;
        m = newm;
        #pragma unroll
        for (int c = 0; c < 32; c++)
            O[row_t * LS + par * 32 + c] *= corr;
        __syncwarp();

        // O += P V (warp strip 16 x 64)
        {
            wmma::fragment<wmma::accumulator, 16, 16, 16, float> oacc[4];
            #pragma unroll
            for (int j = 0; j < 4; j++)
                wmma::load_matrix_sync(oacc[j], O + (wid * 16) * LS + j * 16, LS, wmma::mem_row_major);
            #pragma unroll
            for (int pass = 0; pass < 3; pass++) {
                const __nv_bfloat16* pa = (pass == 2) ? Plo : Phi;
                const __nv_bfloat16* vb = (pass == 1) ? Vlo : Vhi;
                #pragma unroll
                for (int ks = 0; ks < 4; ks++) {
                    wmma::fragment<wmma::matrix_a, 16, 16, 16, __nv_bfloat16, wmma::row_major> a;
                    wmma::load_matrix_sync(a, pa + (wid * 16) * LQ + ks * 16, LQ);
                    #pragma unroll
                    for (int j = 0; j < 4; j++) {
                        wmma::fragment<wmma::matrix_b, 16, 16, 16, __nv_bfloat16, wmma::row_major> bf;
                        wmma::load_matrix_sync(bf, vb + (ks * 16) * LQ + j * 16, LQ);
                        wmma::mma_sync(oacc[j], a, bf, oacc[j]);
                    }
                }
            }
            #pragma unroll
            for (int j = 0; j < 4; j++)
                wmma::store_matrix_sync(O + (wid * 16) * LS + j * 16, oacc[j], LS, wmma::mem_row_major);
        }
        __syncthreads();
    }

    float invl = 1.0f / l;
    size_t orow = (size_t)(b * SS + qt * QROWS + row_t) * EMB + h * DK;
    #pragma unroll
    for (int g = 0; g < 4; g++) {
        int c0 = par * 32 + g * 8;
        const float* sp = O + row_t * LS + c0;
        ushort4 uh, ul, uh2, ul2;
        split1(sp[0] * invl, uh.x, ul.x); split1(sp[1] * invl, uh.y, ul.y);
        split1(sp[2] * invl, uh.z, ul.z); split1(sp[3] * invl, uh.w, ul.w);
        split1(sp[4] * invl, uh2.x, ul2.x); split1(sp[5] * invl, uh2.y, ul2.y);
        split1(sp[6] * invl, uh2.z, ul2.z); split1(sp[7] * invl, uh2.w, ul2.w);
        *(ushort4*)(g_ohi + orow + c0) = uh;
        *(ushort4*)(g_olo + orow + c0) = ul;
        *(ushort4*)(g_ohi + orow + c0 + 4) = uh2;
        *(ushort4*)(g_olo + orow + c0 + 4) = ul2;
    }
}

// ------------------------------- launch ------------------------------------
extern "C" void kernel_launch(void* const* d_in, const int* in_sizes, int n_in,
                              void* d_out, int out_size)
{
    const float* x    = (const float*)d_in[0];
    const int*   mask = (const int*)d_in[1];
    const float* wq   = (const float*)d_in[2];
    const float* wk   = (const float*)d_in[3];
    const float* wv   = (const float*)d_in[4];
    const float* wo   = (const float*)d_in[5];
    float* out = (float*)d_out;

    __nv_bfloat16 *xhi, *xlo, *qhi, *qlo, *khi, *klo, *vhi, *vlo, *ohi, *olo;
    __nv_bfloat16 *wqh, *wql, *wkh, *wkl, *wvh, *wvl, *woh, *wol;
    cudaGetSymbolAddress((void**)&xhi, g_xhi);  cudaGetSymbolAddress((void**)&xlo, g_xlo);
    cudaGetSymbolAddress((void**)&qhi, g_qhi);  cudaGetSymbolAddress((void**)&qlo, g_qlo);
    cudaGetSymbolAddress((void**)&khi, g_khi);  cudaGetSymbolAddress((void**)&klo, g_klo);
    cudaGetSymbolAddress((void**)&vhi, g_vhi);  cudaGetSymbolAddress((void**)&vlo, g_vlo);
    cudaGetSymbolAddress((void**)&ohi, g_ohi);  cudaGetSymbolAddress((void**)&olo, g_olo);
    cudaGetSymbolAddress((void**)&wqh, g_wqhi); cudaGetSymbolAddress((void**)&wql, g_wqlo);
    cudaGetSymbolAddress((void**)&wkh, g_wkhi); cudaGetSymbolAddress((void**)&wkl, g_wklo);
    cudaGetSymbolAddress((void**)&wvh, g_wvhi); cudaGetSymbolAddress((void**)&wvl, g_wvlo);
    cudaGetSymbolAddress((void**)&woh, g_wohi); cudaGetSymbolAddress((void**)&wol, g_wolo);

    cudaFuncSetAttribute(attn_wmma, cudaFuncAttributeMaxDynamicSharedMemorySize, ATTN_SMEM);

    const int nx4 = NROW * EMB / 4;
    const int nw4 = EMB * EMB / 4;
    split_bf16<<<nx4 / 256, 256>>>(x,  xhi, xlo, nx4);
    split_bf16<<<nw4 / 256, 256>>>(wq, wqh, wql, nw4);
    split_bf16<<<nw4 / 256, 256>>>(wk, wkh, wkl, nw4);
    split_bf16<<<nw4 / 256, 256>>>(wv, wvh, wvl, nw4);
    split_bf16<<<nw4 / 256, 256>>>(wo, woh, wol, nw4);

    dim3 gg(EMB / 128, NROW / 128);     // (8, 32)
    gemm_bf16hl<true><<<gg, 128>>>(xhi, xlo, wqh, wql, nullptr, qhi, qlo, NROW, EMB, EMB);
    gemm_bf16hl<true><<<gg, 128>>>(xhi, xlo, wkh, wkl, nullptr, khi, klo, NROW, EMB, EMB);
    gemm_bf16hl<true><<<gg, 128>>>(xhi, xlo, wvh, wvl, nullptr, vhi, vlo, NROW, EMB, EMB);

    attn_wmma<<<dim3(SS / QROWS, NH, BB), 128, ATTN_SMEM>>>(mask);

    gemm_bf16hl<false><<<gg, 128>>>(ohi, olo, woh, wol, out, nullptr, nullptr, NROW, EMB, EMB);
}